// round 15
// baseline (speedup 1.0000x reference)
#include <cuda_runtime.h>
#include <cuda_fp16.h>
#include <cstdint>
#include <math_constants.h>

// logits = x[16384,1024] @ cb[8192,1024]^T ; argmax over codes ; gather cb row.
// Phase 0: fused f32->f16 conversion (x and cb), high-ILP.
// Phase 1: fp16 mma.sync GEMM (fp16 acc), 128x256 CTA tile, 2 CTAs/SM,
//          fully unrolled K loop; fused screening epilogue.
// Phase 2: warp-per-row selection (+ exact fp32 rescore when ambiguous).
// Phase 3: dedicated streaming gather kernel.

#define M_TOTAL 16384
#define N_CODES 8192
#define K_DIM   1024

#define BM 128
#define BN 256
#define BK 64
#define STAGES 2
#define KT_ITERS (K_DIM / BK)   // 16
#define NTILE (N_CODES / BN)    // 32

#define MARGIN 1.5f
#define CAP 8          // candidate slots per (row, tile)
#define RCAP 64        // rescore list cap per row
#define ROWS_PER_BLK 8 // select rows per 256-thread block

// ---- static device buffers ----
__device__ uint4 g_xh4[(size_t)M_TOTAL * K_DIM / 8];    // fp16 x   (32 MB)
__device__ uint4 g_cbh4[(size_t)N_CODES * K_DIM / 8];   // fp16 cb  (16 MB)
__device__ int   g_ccnt[(size_t)M_TOTAL * NTILE];       // counts   (2 MB)
__device__ uint2 g_cand[(size_t)M_TOTAL * NTILE * CAP]; // {val,idx} (33 MB)
__device__ int   g_best[M_TOTAL];                       // winning code per row

#define SWZ(b) ((b) ^ (((b) >> 3) & 0x70))

__device__ __forceinline__ uint32_t s2u(const void* p) {
    return (uint32_t)__cvta_generic_to_shared(p);
}
__device__ __forceinline__ void cpasync16(uint32_t dst, const void* src) {
    asm volatile("cp.async.cg.shared.global [%0], [%1], 16;" :: "r"(dst), "l"(src));
}
__device__ __forceinline__ void ldsm4(uint32_t& r0, uint32_t& r1, uint32_t& r2,
                                      uint32_t& r3, uint32_t addr) {
    asm volatile("ldmatrix.sync.aligned.m8n8.x4.shared.b16 {%0,%1,%2,%3}, [%4];"
                 : "=r"(r0), "=r"(r1), "=r"(r2), "=r"(r3) : "r"(addr));
}
__device__ __forceinline__ void mma16816_f16(uint32_t* c, const uint32_t* a,
                                             const uint32_t* b) {
    asm volatile(
        "mma.sync.aligned.m16n8k16.row.col.f16.f16.f16.f16 "
        "{%0,%1}, {%2,%3,%4,%5}, {%6,%7}, {%0,%1};"
        : "+r"(c[0]), "+r"(c[1])
        : "r"(a[0]), "r"(a[1]), "r"(a[2]), "r"(a[3]), "r"(b[0]), "r"(b[1]));
}

// ---------------------------------------------------------------------------
// Phase 0: fused f32 -> f16. Each thread emits 4 uint4 (8 float4 loads).
// ---------------------------------------------------------------------------
#define NX4  (M_TOTAL * K_DIM / 8)     // 2M uint4 in g_xh4
#define NC4  (N_CODES * K_DIM / 8)     // 1M uint4 in g_cbh4
#define NTHREADS_CVT ((NX4 + NC4) / 4) // 768K

__device__ __forceinline__ uint4 cvt8(float4 a, float4 b) {
    __half2 h0 = __floats2half2_rn(a.x, a.y), h1 = __floats2half2_rn(a.z, a.w);
    __half2 h2 = __floats2half2_rn(b.x, b.y), h3 = __floats2half2_rn(b.z, b.w);
    uint4 o;
    o.x = *(uint32_t*)&h0; o.y = *(uint32_t*)&h1;
    o.z = *(uint32_t*)&h2; o.w = *(uint32_t*)&h3;
    return o;
}
__global__ __launch_bounds__(512)
void cvt_all_kernel(const float* __restrict__ x, const float* __restrict__ cb) {
    const int i = blockIdx.x * blockDim.x + threadIdx.x;
    if (i >= NTHREADS_CVT) return;
    const float4* s;
    uint4* d;
    if (i < NX4 / 4) {
        s = (const float4*)x + (size_t)i * 8;
        d = &g_xh4[(size_t)i * 4];
    } else {
        const int j = i - NX4 / 4;
        s = (const float4*)cb + (size_t)j * 8;
        d = &g_cbh4[(size_t)j * 4];
    }
    float4 a0 = s[0], a1 = s[1], a2 = s[2], a3 = s[3];
    float4 a4 = s[4], a5 = s[5], a6 = s[6], a7 = s[7];
    d[0] = cvt8(a0, a1);
    d[1] = cvt8(a2, a3);
    d[2] = cvt8(a4, a5);
    d[3] = cvt8(a6, a7);
}

// ---------------------------------------------------------------------------
// Phase 1: fp16 GEMM (fp16 acc) 128x256, BK=64, 2-stage pipeline, 8 warps
// (2m x 4n, warp tile 64x64), 2 CTAs/SM. kt fully unrolled.
// ---------------------------------------------------------------------------
__global__ __launch_bounds__(256, 2)
void gemm_f16_kernel() {
    extern __shared__ char smem[];
    const int tid = threadIdx.x;
    const int wid = tid >> 5, lane = tid & 31;
    const int wm = wid >> 2, wn = wid & 3;          // wm 0..1, wn 0..3
    const int m0 = blockIdx.y * BM, n0 = blockIdx.x * BN;
    const __half* xh  = (const __half*)g_xh4;
    const __half* cbh = (const __half*)g_cbh4;

    char* sA = smem;                         // STAGES * 128*128B = 32KB
    char* sB = smem + STAGES * BM * 128;     // STAGES * 256*128B = 64KB

    uint32_t acc[4][8][2];
#pragma unroll
    for (int mi = 0; mi < 4; ++mi)
#pragma unroll
        for (int ni = 0; ni < 8; ++ni) { acc[mi][ni][0] = 0u; acc[mi][ni][1] = 0u; }

    auto load_stage = [&](int s, int kt) {
#pragma unroll
        for (int q = 0; q < 4; ++q) {           // A: 1024 16B chunks
            int f = tid + 256 * q;
            int row = f >> 3, kc = f & 7;
            uint32_t d = s2u(sA + s * BM * 128 + SWZ(row * 128 + kc * 16));
            cpasync16(d, xh + (size_t)(m0 + row) * K_DIM + kt * BK + kc * 8);
        }
#pragma unroll
        for (int q = 0; q < 8; ++q) {           // B: 2048 16B chunks
            int f = tid + 256 * q;
            int row = f >> 3, kc = f & 7;
            uint32_t d = s2u(sB + s * BN * 128 + SWZ(row * 128 + kc * 16));
            cpasync16(d, cbh + (size_t)(n0 + row) * K_DIM + kt * BK + kc * 8);
        }
    };

    load_stage(0, 0);
    asm volatile("cp.async.commit_group;");

#pragma unroll
    for (int kt = 0; kt < KT_ITERS; ++kt) {
        asm volatile("cp.async.wait_group 0;");
        __syncthreads();          // stage kt visible; compute(kt-1) done
        if (kt + 1 < KT_ITERS) load_stage((kt + 1) % STAGES, kt + 1);
        asm volatile("cp.async.commit_group;");

        char* bA = sA + (kt % STAGES) * BM * 128;
        char* bB = sB + (kt % STAGES) * BN * 128;
#pragma unroll
        for (int ks = 0; ks < 4; ++ks) {
            uint32_t afr[4][4];
#pragma unroll
            for (int mi = 0; mi < 4; ++mi) {
                int row = wm * 64 + mi * 16 + (lane & 15);
                int col = ks * 32 + ((lane >> 4) << 4);
                ldsm4(afr[mi][0], afr[mi][1], afr[mi][2], afr[mi][3],
                      s2u(bA + SWZ(row * 128 + col)));
            }
            uint32_t bfr[8][2];
#pragma unroll
            for (int pi = 0; pi < 4; ++pi) {
                int row = wn * 64 + pi * 16 + ((lane >> 4) << 3) + (lane & 7);
                int col = ks * 32 + ((lane >> 3) & 1) * 16;
                uint32_t r0, r1, r2, r3;
                ldsm4(r0, r1, r2, r3, s2u(bB + SWZ(row * 128 + col)));
                bfr[2 * pi][0] = r0; bfr[2 * pi][1] = r1;
                bfr[2 * pi + 1][0] = r2; bfr[2 * pi + 1][1] = r3;
            }
#pragma unroll
            for (int mi = 0; mi < 4; ++mi)
#pragma unroll
                for (int ni = 0; ni < 8; ++ni)
                    mma16816_f16(acc[mi][ni], afr[mi], bfr[ni]);
        }
    }
    __syncthreads();   // tile reads done everywhere; reuse smem for epilogue

    // ---- fused epilogue ----
    // f16-acc fragment: reg h -> row r = wm*64 + mi*16 + h*8 + (lane>>2);
    //                   packed cols c = wn*64 + ni*8 + (lane&3)*2 + {0,1}
    float* s_wmax = (float*)smem;                 // [128][4]    2KB
    float* s_rmax = (float*)(smem + 2048);        // [128]       512B
    int*   s_cnt  = (int*)(smem + 2560);          // [128]       512B
    uint2* s_slot = (uint2*)(smem + 3072);        // [128][CAP]  8KB

    if (tid < 128) s_cnt[tid] = 0;

#pragma unroll
    for (int mi = 0; mi < 4; ++mi)
#pragma unroll
        for (int h = 0; h < 2; ++h) {
            float lm = -CUDART_INF_F;
#pragma unroll
            for (int ni = 0; ni < 8; ++ni) {
                float2 v = __half22float2(*(__half2*)&acc[mi][ni][h]);
                lm = fmaxf(lm, fmaxf(v.x, v.y));
            }
            lm = fmaxf(lm, __shfl_xor_sync(~0u, lm, 1));
            lm = fmaxf(lm, __shfl_xor_sync(~0u, lm, 2));
            if ((lane & 3) == 0) {
                int r = wm * 64 + mi * 16 + h * 8 + (lane >> 2);
                s_wmax[r * 4 + wn] = lm;
            }
        }
    __syncthreads();
    if (tid < 128) {
        s_rmax[tid] = fmaxf(fmaxf(s_wmax[tid * 4], s_wmax[tid * 4 + 1]),
                            fmaxf(s_wmax[tid * 4 + 2], s_wmax[tid * 4 + 3]));
    }
    __syncthreads();

#pragma unroll
    for (int mi = 0; mi < 4; ++mi)
#pragma unroll
        for (int h = 0; h < 2; ++h) {
            const int r = wm * 64 + mi * 16 + h * 8 + (lane >> 2);
            const float thr = s_rmax[r] - MARGIN;
#pragma unroll
            for (int ni = 0; ni < 8; ++ni) {
                float2 v2 = __half22float2(*(__half2*)&acc[mi][ni][h]);
#pragma unroll
                for (int jj = 0; jj < 2; ++jj) {
                    float v = jj ? v2.y : v2.x;
                    if (v > thr) {
                        int p = atomicAdd(&s_cnt[r], 1);
                        if (p < CAP) {
                            uint2 e;
                            e.x = __float_as_uint(v);
                            e.y = (uint32_t)(n0 + wn * 64 + ni * 8 + (lane & 3) * 2 + jj);
                            s_slot[r * CAP + p] = e;
                        }
                    }
                }
            }
        }
    __syncthreads();
    if (tid < 128) {
        const int c = s_cnt[tid];
        const size_t base = ((size_t)(m0 + tid) * NTILE + blockIdx.x);
        g_ccnt[base] = c;
        const int cw = c < CAP ? c : CAP;
        for (int p = 0; p < cw; ++p)
            g_cand[base * CAP + p] = s_slot[tid * CAP + p];
    }
}

// ---------------------------------------------------------------------------
// Phase 2: warp-per-row selection + exact fp32 rescore -> g_best[row].
// ---------------------------------------------------------------------------
__global__ __launch_bounds__(256)
void select_kernel(const float* __restrict__ x, const float* __restrict__ cb) {
    const int tid  = threadIdx.x;
    const int w    = tid >> 5;
    const int lane = tid & 31;
    const int row  = blockIdx.x * ROWS_PER_BLK + w;

    __shared__ int s_list[ROWS_PER_BLK][RCAP];
    __shared__ int s_n[ROWS_PER_BLK];

    if (lane == 0) s_n[w] = 0;
    __syncwarp();

    // lane t owns n-tile t (NTILE == 32)
    const size_t tb = (size_t)row * NTILE + lane;
    int cnt = g_ccnt[tb];
    const bool ovf_l = (cnt > CAP);
    if (cnt > CAP) cnt = CAP;
    const uint2* cd = &g_cand[tb * CAP];

    float gmax = -CUDART_INF_F;
    for (int p = 0; p < cnt; ++p)
        gmax = fmaxf(gmax, __uint_as_float(cd[p].x));
#pragma unroll
    for (int o = 16; o; o >>= 1) gmax = fmaxf(gmax, __shfl_xor_sync(~0u, gmax, o));
    const bool ovf = __any_sync(~0u, ovf_l);
    const float thr = gmax - MARGIN;

    float bv = -CUDART_INF_F; int bi = N_CODES;
    for (int p = 0; p < cnt; ++p) {
        const float v = __uint_as_float(cd[p].x);
        if (v > thr) {
            const int q = atomicAdd(&s_n[w], 1);
            if (q < RCAP) s_list[w][q] = (int)cd[p].y;
            if (v > bv || (v == bv && (int)cd[p].y < bi)) { bv = v; bi = (int)cd[p].y; }
        }
    }
#pragma unroll
    for (int o = 16; o; o >>= 1) {
        const float ov = __shfl_xor_sync(~0u, bv, o);
        const int   oi = __shfl_xor_sync(~0u, bi, o);
        if (ov > bv || (ov == bv && oi < bi)) { bv = ov; bi = oi; }
    }
    __syncwarp();
    const int ncand = s_n[w];

    if (!ovf && ncand == 1) {
        if (lane == 0) g_best[row] = bi;
    } else {
        // exact fp32 rescore, warp-cooperative dots (8 float4 per lane)
        const bool full = ovf || (ncand > RCAP);
        const int ntot = full ? N_CODES : ncand;
        const float4* xr = (const float4*)(x + (size_t)row * K_DIM);
        float4 a[8];
#pragma unroll
        for (int it = 0; it < 8; ++it) a[it] = xr[it * 32 + lane];
        float bestv = -CUDART_INF_F; int best = N_CODES;
        for (int ci = 0; ci < ntot; ++ci) {
            const int code = full ? ci : s_list[w][ci];
            const float4* cr = (const float4*)(cb + (size_t)code * K_DIM);
            float p = 0.f;
#pragma unroll
            for (int it = 0; it < 8; ++it) {
                const float4 b = cr[it * 32 + lane];
                p += a[it].x * b.x + a[it].y * b.y + a[it].z * b.z + a[it].w * b.w;
            }
#pragma unroll
            for (int o = 16; o; o >>= 1) p += __shfl_xor_sync(~0u, p, o);
            if (p > bestv || (p == bestv && code < best)) { bestv = p; best = code; }
        }
        if (lane == 0) g_best[row] = best;
    }
}

// ---------------------------------------------------------------------------
// Phase 3: streaming gather. One block per row; minimal registers, max occ.
// ---------------------------------------------------------------------------
__global__ __launch_bounds__(256)
void gather_kernel(const float* __restrict__ cb, float* __restrict__ out) {
    __shared__ int s_code;
    if (threadIdx.x == 0) s_code = g_best[blockIdx.x];
    __syncthreads();
    const float4* src = (const float4*)(cb + (size_t)s_code * K_DIM);
    float4* dst = (float4*)(out + (size_t)blockIdx.x * K_DIM);
    dst[threadIdx.x] = src[threadIdx.x];
}

// ---------------------------------------------------------------------------
extern "C" void kernel_launch(void* const* d_in, const int* in_sizes, int n_in,
                              void* d_out, int out_size) {
    const float* x  = (const float*)d_in[0];   // [8,2048,1024]
    const float* cb = (const float*)d_in[1];   // [8192,1024]
    float* out = (float*)d_out;

    const int smem = STAGES * (BM + BN) * 128; // 98304
    cudaFuncSetAttribute(gemm_f16_kernel,
                         cudaFuncAttributeMaxDynamicSharedMemorySize, smem);

    cvt_all_kernel<<<(NTHREADS_CVT + 511) / 512, 512>>>(x, cb);

    dim3 grid(N_CODES / BN, M_TOTAL / BM);     // (32, 128) = 4096 CTAs
    gemm_f16_kernel<<<grid, 256, smem>>>();

    select_kernel<<<M_TOTAL / ROWS_PER_BLK, 256>>>(x, cb);
    gather_kernel<<<M_TOTAL, 256>>>(cb, out);
}

// round 16
// speedup vs baseline: 1.0209x; 1.0209x over previous
#include <cuda_runtime.h>
#include <cuda_fp16.h>
#include <cstdint>
#include <math_constants.h>

// logits = x[16384,1024] @ cb[8192,1024]^T ; argmax over codes ; gather cb row.
// Phase 0: fused f32->f16 conversion (x and cb)  [R14 measured-best version].
// Phase 1: fp16 mma.sync GEMM (fp16 acc), 128x256 CTA tile, 2 CTAs/SM,
//          fully unrolled K loop; fused screening epilogue.
// Phase 2: warp-per-row selection (+ exact fp32 rescore when ambiguous).
// Phase 3: streaming gather, 8 rows per block for MLP.

#define M_TOTAL 16384
#define N_CODES 8192
#define K_DIM   1024

#define BM 128
#define BN 256
#define BK 64
#define STAGES 2
#define KT_ITERS (K_DIM / BK)   // 16
#define NTILE (N_CODES / BN)    // 32

#define MARGIN 1.5f
#define CAP 8          // candidate slots per (row, tile)
#define RCAP 64        // rescore list cap per row
#define ROWS_PER_BLK 8 // select/gather rows per 256-thread block

// ---- static device buffers ----
__device__ uint4 g_xh4[(size_t)M_TOTAL * K_DIM / 8];    // fp16 x   (32 MB)
__device__ uint4 g_cbh4[(size_t)N_CODES * K_DIM / 8];   // fp16 cb  (16 MB)
__device__ int   g_ccnt[(size_t)M_TOTAL * NTILE];       // counts   (2 MB)
__device__ uint2 g_cand[(size_t)M_TOTAL * NTILE * CAP]; // {val,idx} (33 MB)
__device__ int   g_best[M_TOTAL];                       // winning code per row

#define SWZ(b) ((b) ^ (((b) >> 3) & 0x70))

__device__ __forceinline__ uint32_t s2u(const void* p) {
    return (uint32_t)__cvta_generic_to_shared(p);
}
__device__ __forceinline__ void cpasync16(uint32_t dst, const void* src) {
    asm volatile("cp.async.cg.shared.global [%0], [%1], 16;" :: "r"(dst), "l"(src));
}
__device__ __forceinline__ void ldsm4(uint32_t& r0, uint32_t& r1, uint32_t& r2,
                                      uint32_t& r3, uint32_t addr) {
    asm volatile("ldmatrix.sync.aligned.m8n8.x4.shared.b16 {%0,%1,%2,%3}, [%4];"
                 : "=r"(r0), "=r"(r1), "=r"(r2), "=r"(r3) : "r"(addr));
}
__device__ __forceinline__ void mma16816_f16(uint32_t* c, const uint32_t* a,
                                             const uint32_t* b) {
    asm volatile(
        "mma.sync.aligned.m16n8k16.row.col.f16.f16.f16.f16 "
        "{%0,%1}, {%2,%3,%4,%5}, {%6,%7}, {%0,%1};"
        : "+r"(c[0]), "+r"(c[1])
        : "r"(a[0]), "r"(a[1]), "r"(a[2]), "r"(a[3]), "r"(b[0]), "r"(b[1]));
}

// ---------------------------------------------------------------------------
// Phase 0: fused f32 -> f16 (R14 version: 2 uint4/thread, __ldcs).
// ---------------------------------------------------------------------------
#define NX4  (M_TOTAL * K_DIM / 8)     // 2M uint4 in g_xh4
#define NC4  (N_CODES * K_DIM / 8)     // 1M uint4 in g_cbh4
#define NTHREADS_CVT ((NX4 + NC4) / 2) // 1.5M

__device__ __forceinline__ uint4 cvt8(float4 a, float4 b) {
    __half2 h0 = __floats2half2_rn(a.x, a.y), h1 = __floats2half2_rn(a.z, a.w);
    __half2 h2 = __floats2half2_rn(b.x, b.y), h3 = __floats2half2_rn(b.z, b.w);
    uint4 o;
    o.x = *(uint32_t*)&h0; o.y = *(uint32_t*)&h1;
    o.z = *(uint32_t*)&h2; o.w = *(uint32_t*)&h3;
    return o;
}
__global__ __launch_bounds__(256)
void cvt_all_kernel(const float* __restrict__ x, const float* __restrict__ cb) {
    const int i = blockIdx.x * blockDim.x + threadIdx.x;
    if (i >= NTHREADS_CVT) return;
    if (i < NX4 / 2) {
        const float4* s = (const float4*)x + (size_t)i * 4;
        float4 a0 = __ldcs(s), a1 = __ldcs(s + 1), a2 = __ldcs(s + 2), a3 = __ldcs(s + 3);
        g_xh4[2 * i]     = cvt8(a0, a1);
        g_xh4[2 * i + 1] = cvt8(a2, a3);
    } else {
        const int j = i - NX4 / 2;
        const float4* s = (const float4*)cb + (size_t)j * 4;
        float4 a0 = __ldcs(s), a1 = __ldcs(s + 1), a2 = __ldcs(s + 2), a3 = __ldcs(s + 3);
        g_cbh4[2 * j]     = cvt8(a0, a1);
        g_cbh4[2 * j + 1] = cvt8(a2, a3);
    }
}

// ---------------------------------------------------------------------------
// Phase 1: fp16 GEMM (fp16 acc) 128x256, BK=64, 2-stage pipeline, 8 warps
// (2m x 4n, warp tile 64x64), 2 CTAs/SM. kt fully unrolled.
// ---------------------------------------------------------------------------
__global__ __launch_bounds__(256, 2)
void gemm_f16_kernel() {
    extern __shared__ char smem[];
    const int tid = threadIdx.x;
    const int wid = tid >> 5, lane = tid & 31;
    const int wm = wid >> 2, wn = wid & 3;          // wm 0..1, wn 0..3
    const int m0 = blockIdx.y * BM, n0 = blockIdx.x * BN;
    const __half* xh  = (const __half*)g_xh4;
    const __half* cbh = (const __half*)g_cbh4;

    char* sA = smem;                         // STAGES * 128*128B = 32KB
    char* sB = smem + STAGES * BM * 128;     // STAGES * 256*128B = 64KB

    uint32_t acc[4][8][2];
#pragma unroll
    for (int mi = 0; mi < 4; ++mi)
#pragma unroll
        for (int ni = 0; ni < 8; ++ni) { acc[mi][ni][0] = 0u; acc[mi][ni][1] = 0u; }

    auto load_stage = [&](int s, int kt) {
#pragma unroll
        for (int q = 0; q < 4; ++q) {           // A: 1024 16B chunks
            int f = tid + 256 * q;
            int row = f >> 3, kc = f & 7;
            uint32_t d = s2u(sA + s * BM * 128 + SWZ(row * 128 + kc * 16));
            cpasync16(d, xh + (size_t)(m0 + row) * K_DIM + kt * BK + kc * 8);
        }
#pragma unroll
        for (int q = 0; q < 8; ++q) {           // B: 2048 16B chunks
            int f = tid + 256 * q;
            int row = f >> 3, kc = f & 7;
            uint32_t d = s2u(sB + s * BN * 128 + SWZ(row * 128 + kc * 16));
            cpasync16(d, cbh + (size_t)(n0 + row) * K_DIM + kt * BK + kc * 8);
        }
    };

    load_stage(0, 0);
    asm volatile("cp.async.commit_group;");

#pragma unroll
    for (int kt = 0; kt < KT_ITERS; ++kt) {
        asm volatile("cp.async.wait_group 0;");
        __syncthreads();          // stage kt visible; compute(kt-1) done
        if (kt + 1 < KT_ITERS) load_stage((kt + 1) % STAGES, kt + 1);
        asm volatile("cp.async.commit_group;");

        char* bA = sA + (kt % STAGES) * BM * 128;
        char* bB = sB + (kt % STAGES) * BN * 128;
#pragma unroll
        for (int ks = 0; ks < 4; ++ks) {
            uint32_t afr[4][4];
#pragma unroll
            for (int mi = 0; mi < 4; ++mi) {
                int row = wm * 64 + mi * 16 + (lane & 15);
                int col = ks * 32 + ((lane >> 4) << 4);
                ldsm4(afr[mi][0], afr[mi][1], afr[mi][2], afr[mi][3],
                      s2u(bA + SWZ(row * 128 + col)));
            }
            uint32_t bfr[8][2];
#pragma unroll
            for (int pi = 0; pi < 4; ++pi) {
                int row = wn * 64 + pi * 16 + ((lane >> 4) << 3) + (lane & 7);
                int col = ks * 32 + ((lane >> 3) & 1) * 16;
                uint32_t r0, r1, r2, r3;
                ldsm4(r0, r1, r2, r3, s2u(bB + SWZ(row * 128 + col)));
                bfr[2 * pi][0] = r0; bfr[2 * pi][1] = r1;
                bfr[2 * pi + 1][0] = r2; bfr[2 * pi + 1][1] = r3;
            }
#pragma unroll
            for (int mi = 0; mi < 4; ++mi)
#pragma unroll
                for (int ni = 0; ni < 8; ++ni)
                    mma16816_f16(acc[mi][ni], afr[mi], bfr[ni]);
        }
    }
    __syncthreads();   // tile reads done everywhere; reuse smem for epilogue

    // ---- fused epilogue ----
    // f16-acc fragment: reg h -> row r = wm*64 + mi*16 + h*8 + (lane>>2);
    //                   packed cols c = wn*64 + ni*8 + (lane&3)*2 + {0,1}
    float* s_wmax = (float*)smem;                 // [128][4]    2KB
    float* s_rmax = (float*)(smem + 2048);        // [128]       512B
    int*   s_cnt  = (int*)(smem + 2560);          // [128]       512B
    uint2* s_slot = (uint2*)(smem + 3072);        // [128][CAP]  8KB

    if (tid < 128) s_cnt[tid] = 0;

#pragma unroll
    for (int mi = 0; mi < 4; ++mi)
#pragma unroll
        for (int h = 0; h < 2; ++h) {
            float lm = -CUDART_INF_F;
#pragma unroll
            for (int ni = 0; ni < 8; ++ni) {
                float2 v = __half22float2(*(__half2*)&acc[mi][ni][h]);
                lm = fmaxf(lm, fmaxf(v.x, v.y));
            }
            lm = fmaxf(lm, __shfl_xor_sync(~0u, lm, 1));
            lm = fmaxf(lm, __shfl_xor_sync(~0u, lm, 2));
            if ((lane & 3) == 0) {
                int r = wm * 64 + mi * 16 + h * 8 + (lane >> 2);
                s_wmax[r * 4 + wn] = lm;
            }
        }
    __syncthreads();
    if (tid < 128) {
        s_rmax[tid] = fmaxf(fmaxf(s_wmax[tid * 4], s_wmax[tid * 4 + 1]),
                            fmaxf(s_wmax[tid * 4 + 2], s_wmax[tid * 4 + 3]));
    }
    __syncthreads();

#pragma unroll
    for (int mi = 0; mi < 4; ++mi)
#pragma unroll
        for (int h = 0; h < 2; ++h) {
            const int r = wm * 64 + mi * 16 + h * 8 + (lane >> 2);
            const float thr = s_rmax[r] - MARGIN;
#pragma unroll
            for (int ni = 0; ni < 8; ++ni) {
                float2 v2 = __half22float2(*(__half2*)&acc[mi][ni][h]);
#pragma unroll
                for (int jj = 0; jj < 2; ++jj) {
                    float v = jj ? v2.y : v2.x;
                    if (v > thr) {
                        int p = atomicAdd(&s_cnt[r], 1);
                        if (p < CAP) {
                            uint2 e;
                            e.x = __float_as_uint(v);
                            e.y = (uint32_t)(n0 + wn * 64 + ni * 8 + (lane & 3) * 2 + jj);
                            s_slot[r * CAP + p] = e;
                        }
                    }
                }
            }
        }
    __syncthreads();
    if (tid < 128) {
        const int c = s_cnt[tid];
        const size_t base = ((size_t)(m0 + tid) * NTILE + blockIdx.x);
        g_ccnt[base] = c;
        const int cw = c < CAP ? c : CAP;
        for (int p = 0; p < cw; ++p)
            g_cand[base * CAP + p] = s_slot[tid * CAP + p];
    }
}

// ---------------------------------------------------------------------------
// Phase 2: warp-per-row selection + exact fp32 rescore -> g_best[row].
// ---------------------------------------------------------------------------
__global__ __launch_bounds__(256)
void select_kernel(const float* __restrict__ x, const float* __restrict__ cb) {
    const int tid  = threadIdx.x;
    const int w    = tid >> 5;
    const int lane = tid & 31;
    const int row  = blockIdx.x * ROWS_PER_BLK + w;

    __shared__ int s_list[ROWS_PER_BLK][RCAP];
    __shared__ int s_n[ROWS_PER_BLK];

    if (lane == 0) s_n[w] = 0;
    __syncwarp();

    // lane t owns n-tile t (NTILE == 32)
    const size_t tb = (size_t)row * NTILE + lane;
    int cnt = g_ccnt[tb];
    const bool ovf_l = (cnt > CAP);
    if (cnt > CAP) cnt = CAP;
    const uint2* cd = &g_cand[tb * CAP];

    float gmax = -CUDART_INF_F;
    for (int p = 0; p < cnt; ++p)
        gmax = fmaxf(gmax, __uint_as_float(cd[p].x));
#pragma unroll
    for (int o = 16; o; o >>= 1) gmax = fmaxf(gmax, __shfl_xor_sync(~0u, gmax, o));
    const bool ovf = __any_sync(~0u, ovf_l);
    const float thr = gmax - MARGIN;

    float bv = -CUDART_INF_F; int bi = N_CODES;
    for (int p = 0; p < cnt; ++p) {
        const float v = __uint_as_float(cd[p].x);
        if (v > thr) {
            const int q = atomicAdd(&s_n[w], 1);
            if (q < RCAP) s_list[w][q] = (int)cd[p].y;
            if (v > bv || (v == bv && (int)cd[p].y < bi)) { bv = v; bi = (int)cd[p].y; }
        }
    }
#pragma unroll
    for (int o = 16; o; o >>= 1) {
        const float ov = __shfl_xor_sync(~0u, bv, o);
        const int   oi = __shfl_xor_sync(~0u, bi, o);
        if (ov > bv || (ov == bv && oi < bi)) { bv = ov; bi = oi; }
    }
    __syncwarp();
    const int ncand = s_n[w];

    if (!ovf && ncand == 1) {
        if (lane == 0) g_best[row] = bi;
    } else {
        // exact fp32 rescore, warp-cooperative dots (8 float4 per lane)
        const bool full = ovf || (ncand > RCAP);
        const int ntot = full ? N_CODES : ncand;
        const float4* xr = (const float4*)(x + (size_t)row * K_DIM);
        float4 a[8];
#pragma unroll
        for (int it = 0; it < 8; ++it) a[it] = xr[it * 32 + lane];
        float bestv = -CUDART_INF_F; int best = N_CODES;
        for (int ci = 0; ci < ntot; ++ci) {
            const int code = full ? ci : s_list[w][ci];
            const float4* cr = (const float4*)(cb + (size_t)code * K_DIM);
            float p = 0.f;
#pragma unroll
            for (int it = 0; it < 8; ++it) {
                const float4 b = cr[it * 32 + lane];
                p += a[it].x * b.x + a[it].y * b.y + a[it].z * b.z + a[it].w * b.w;
            }
#pragma unroll
            for (int o = 16; o; o >>= 1) p += __shfl_xor_sync(~0u, p, o);
            if (p > bestv || (p == bestv && code < best)) { bestv = p; best = code; }
        }
        if (lane == 0) g_best[row] = best;
    }
}

// ---------------------------------------------------------------------------
// Phase 3: streaming gather, 8 rows per block (8x MLP per thread).
// ---------------------------------------------------------------------------
__global__ __launch_bounds__(256)
void gather_kernel(const float* __restrict__ cb, float* __restrict__ out) {
    __shared__ int s_code[ROWS_PER_BLK];
    const int r0 = blockIdx.x * ROWS_PER_BLK;
    if (threadIdx.x < ROWS_PER_BLK) s_code[threadIdx.x] = g_best[r0 + threadIdx.x];
    __syncthreads();
#pragma unroll
    for (int r = 0; r < ROWS_PER_BLK; ++r) {
        const float4* src = (const float4*)(cb + (size_t)s_code[r] * K_DIM);
        float4* dst = (float4*)(out + (size_t)(r0 + r) * K_DIM);
        dst[threadIdx.x] = src[threadIdx.x];
    }
}

// ---------------------------------------------------------------------------
extern "C" void kernel_launch(void* const* d_in, const int* in_sizes, int n_in,
                              void* d_out, int out_size) {
    const float* x  = (const float*)d_in[0];   // [8,2048,1024]
    const float* cb = (const float*)d_in[1];   // [8192,1024]
    float* out = (float*)d_out;

    const int smem = STAGES * (BM + BN) * 128; // 98304
    cudaFuncSetAttribute(gemm_f16_kernel,
                         cudaFuncAttributeMaxDynamicSharedMemorySize, smem);

    cvt_all_kernel<<<(NTHREADS_CVT + 255) / 256, 256>>>(x, cb);

    dim3 grid(N_CODES / BN, M_TOTAL / BM);     // (32, 128) = 4096 CTAs
    gemm_f16_kernel<<<grid, 256, smem>>>();

    select_kernel<<<M_TOTAL / ROWS_PER_BLK, 256>>>(x, cb);
    gather_kernel<<<M_TOTAL / ROWS_PER_BLK, 256>>>(cb, out);
}